// round 10
// baseline (speedup 1.0000x reference)
#include <cuda_runtime.h>
#include <cstdint>

#define NB 4
#define NA (1 << 20)
#define BPB 256                      // scan blocks per batch
#define NBLOCKS (NB * BPB)           // 1024
#define NTHREADS 256
#define ROWS_PER_BLOCK (NA / BPB)    // 4096 rows (props) per block
#define QUADS_PER_THREAD (ROWS_PER_BLOCK / 4 / NTHREADS)  // 4

// scratch: per block, 4 u64 keys: [col0_top1, col0_top2, col1_top1, col1_top2]
__device__ unsigned long long g_scratch[NBLOCKS * 4];

__device__ __forceinline__ unsigned long long make_key(float v, unsigned int idx) {
    // high 32: float bits of positive score (order-preserving for positives)
    // low 32 : ~idx  (ties in score -> smaller index = larger key)
    return (((unsigned long long)__float_as_uint(v)) << 32) | (unsigned long long)(~idx);
}

__device__ __forceinline__ void upd2(unsigned long long& a1, unsigned long long& a2,
                                     unsigned long long k) {
    if (k > a1) { a2 = a1; a1 = k; }
    else if (k > a2) { a2 = k; }
}

// merge top-2 list (b1>=b2) into (a1>=a2)
__device__ __forceinline__ void merge2(unsigned long long& a1, unsigned long long& a2,
                                       unsigned long long b1, unsigned long long b2) {
    unsigned long long hi = a1 > b1 ? a1 : b1;
    unsigned long long lo = a1 > b1 ? b1 : a1;
    unsigned long long m2 = a2 > b2 ? a2 : b2;
    a1 = hi;
    a2 = lo > m2 ? lo : m2;
}

// Pass 1: per-(batch,class) top-2 scan. NOT fully unrolled: keeping the quad
// loop as a real loop limits front-batched LDGs (MLP_p1 = 3 instead of 12),
// which per the B300 spread model collapses the cross-CTA L1tex-queue
// straggler tail (spr_max ~2.0 -> ~1.1) that otherwise sets kernel end time.
__global__ void __launch_bounds__(NTHREADS) pass1_top2(const float* __restrict__ probs) {
    const int tid   = threadIdx.x;
    const int blk   = blockIdx.x;
    const int batch = blk >> 8;        // / BPB
    const int chunk = blk & (BPB - 1);
    const long long row0 = (long long)batch * NA + (long long)chunk * ROWS_PER_BLOCK;
    const float4* __restrict__ p4 = reinterpret_cast<const float4*>(probs);

    unsigned long long k0a = 0, k0b = 0;  // class column 0 (cls=1)
    unsigned long long k1a = 0, k1b = 0;  // class column 1 (cls=2)

#pragma unroll 1
    for (int it = 0; it < QUADS_PER_THREAD; ++it) {
        const long long row = row0 + (long long)(it * NTHREADS + tid) * 4;
        const long long f4  = (row >> 2) * 3;  // row*3/4, row % 4 == 0
        const float4 A = p4[f4];
        const float4 B = p4[f4 + 1];
        const float4 C = p4[f4 + 2];
        // A = {r0c0,r0c1,r0c2,r1c0}, B = {r1c1,r1c2,r2c0,r2c1}, C = {r2c2,r3c0,r3c1,r3c2}
        const unsigned int i0 = (unsigned int)(row * 2);  // fg flat index of (row, col0)
        upd2(k0a, k0b, make_key(A.y, i0 + 0));
        upd2(k1a, k1b, make_key(A.z, i0 + 1));
        upd2(k0a, k0b, make_key(B.x, i0 + 2));
        upd2(k1a, k1b, make_key(B.y, i0 + 3));
        upd2(k0a, k0b, make_key(B.w, i0 + 4));
        upd2(k1a, k1b, make_key(C.x, i0 + 5));
        upd2(k0a, k0b, make_key(C.z, i0 + 6));
        upd2(k1a, k1b, make_key(C.w, i0 + 7));
    }

    __shared__ unsigned long long s[NTHREADS][4];
    s[tid][0] = k0a;
    s[tid][1] = k0b;
    s[tid][2] = k1a;
    s[tid][3] = k1b;
    __syncthreads();

    for (int off = NTHREADS / 2; off > 0; off >>= 1) {
        if (tid < off) {
            unsigned long long a1 = s[tid][0], a2 = s[tid][1];
            merge2(a1, a2, s[tid + off][0], s[tid + off][1]);
            s[tid][0] = a1; s[tid][1] = a2;
            unsigned long long c1 = s[tid][2], c2 = s[tid][3];
            merge2(c1, c2, s[tid + off][2], s[tid + off][3]);
            s[tid][2] = c1; s[tid][3] = c2;
        }
        __syncthreads();
    }

    if (tid == 0) {
#pragma unroll
        for (int j = 0; j < 4; ++j) g_scratch[blk * 4 + j] = s[0][j];
    }
}

// Pass 2: reduce scratch -> 16 keys; rank sort; decode; write 16x9.
// batch index computed arithmetically (batch_ixs = repeat(arange(NB), NA)),
// gathers vectorized as float2 to shorten the dependent-load chain.
__global__ void __launch_bounds__(256) pass2_decode(const float* __restrict__ anchors,
                                                    const float* __restrict__ deltas,
                                                    float* __restrict__ out) {
    __shared__ unsigned long long gtop[16];
    const int tid  = threadIdx.x;
    const int warp = tid >> 5;
    const int lane = tid & 31;

    // 8 warps, one per (batch, class) group
    {
        const int batch = warp >> 1;
        const int col   = warp & 1;
        unsigned long long a1 = 0, a2 = 0;
#pragma unroll
        for (int b = 0; b < BPB / 32; ++b) {
            const int blk = batch * BPB + b * 32 + lane;
            merge2(a1, a2, g_scratch[blk * 4 + col * 2], g_scratch[blk * 4 + col * 2 + 1]);
        }
#pragma unroll
        for (int off = 16; off > 0; off >>= 1) {
            unsigned long long b1 = __shfl_down_sync(0xffffffffu, a1, off);
            unsigned long long b2 = __shfl_down_sync(0xffffffffu, a2, off);
            merge2(a1, a2, b1, b2);
        }
        if (lane == 0) { gtop[warp * 2] = a1; gtop[warp * 2 + 1] = a2; }
    }
    __syncthreads();

    if (tid < 16) {
        // rank sort: all 16 keys distinct (unique index in low bits)
        const unsigned long long key = gtop[tid];
        int rank = 0;
#pragma unroll
        for (int j = 0; j < 16; ++j) rank += (gtop[j] > key) ? 1 : 0;

        const unsigned int flat = ~((unsigned int)key);        // fg flat index
        const int prop = (int)(flat >> 1);
        const int cls  = (int)(flat & 1u) + 1;
        const float score = __uint_as_float((unsigned int)(key >> 32));
        const int b_ix = prop >> 20;           // batch_ixs = repeat(arange(NB), NA)
        const int aidx = prop & (NA - 1);

        const float scale[6] = {256.f, 256.f, 256.f, 256.f, 128.f, 128.f};
        const float stdv[6]  = {0.1f, 0.1f, 0.1f, 0.2f, 0.2f, 0.2f};

        // vectorized gathers: rows are 6 floats = 24B, 8B-aligned -> 3x float2
        const float2* __restrict__ a2p = reinterpret_cast<const float2*>(anchors) +
                                         (long long)aidx * 3;
        const float2* __restrict__ d2p = reinterpret_cast<const float2*>(deltas) +
                                         (long long)prop * 3;
        const float2 av0 = a2p[0], av1 = a2p[1], av2 = a2p[2];
        const float2 dv0 = d2p[0], dv1 = d2p[1], dv2 = d2p[2];

        float anc[6] = {av0.x, av0.y, av1.x, av1.y, av2.x, av2.y};
        float dl [6] = {dv0.x, dv0.y, dv1.x, dv1.y, dv2.x, dv2.y};
#pragma unroll
        for (int j = 0; j < 6; ++j) anc[j] = floorf(anc[j] / scale[j]);
#pragma unroll
        for (int j = 0; j < 6; ++j) dl[j] *= stdv[j];

        float h = anc[2] - anc[0];
        float w = anc[3] - anc[1];
        float d = anc[5] - anc[4];
        float cy = anc[0] + 0.5f * h + dl[0] * h;
        float cx = anc[1] + 0.5f * w + dl[1] * w;
        float cz = anc[4] + 0.5f * d + dl[2] * d;
        h *= expf(dl[3]);
        w *= expf(dl[4]);
        d *= expf(dl[5]);

        float box[6];
        box[0] = cy - 0.5f * h;
        box[1] = cx - 0.5f * w;
        box[2] = box[0] + h;
        box[3] = box[1] + w;
        box[4] = cz - 0.5f * d;
        box[5] = box[4] + d;

        float* o = out + rank * 9;   // each thread writes its sorted slot
#pragma unroll
        for (int j = 0; j < 6; ++j)
            o[j] = rintf(fminf(fmaxf(box[j] * scale[j], 0.0f), scale[j]));
        o[6] = (float)b_ix;
        o[7] = (float)cls;
        o[8] = score;
    }
}

extern "C" void kernel_launch(void* const* d_in, const int* in_sizes, int n_in,
                              void* d_out, int out_size) {
    // identify inputs by element count (robust to ordering)
    const float* anchors = nullptr;   // NA*6       = 6,291,456
    const float* probs   = nullptr;   // NB*NA*3    = 12,582,912
    const float* deltas  = nullptr;   // NB*NA*6    = 25,165,824
    for (int i = 0; i < n_in; ++i) {
        switch (in_sizes[i]) {
            case 6291456:  anchors = (const float*)d_in[i]; break;
            case 12582912: probs   = (const float*)d_in[i]; break;
            case 25165824: deltas  = (const float*)d_in[i]; break;
            default: break;
        }
    }

    pass1_top2<<<NBLOCKS, NTHREADS>>>(probs);
    pass2_decode<<<1, 256>>>(anchors, deltas, (float*)d_out);
}

// round 11
// speedup vs baseline: 1.1547x; 1.1547x over previous
#include <cuda_runtime.h>
#include <cstdint>

#define NB 4
#define NA (1 << 20)
#define BPB 256                      // scan blocks per batch
#define NBLOCKS (NB * BPB)           // 1024
#define NTHREADS 256
#define ROWS_PER_BLOCK (NA / BPB)    // 4096 rows (props) per block
#define QUADS_PER_THREAD (ROWS_PER_BLOCK / 4 / NTHREADS)  // 4

// scratch: per block, 4 u64 keys: [col0_top1, col0_top2, col1_top1, col1_top2]
__device__ unsigned long long g_scratch[NBLOCKS * 4];

__device__ __forceinline__ unsigned long long make_key(float v, unsigned int idx) {
    // high 32: float bits of positive score (order-preserving for positives)
    // low 32 : ~idx  (ties in score -> smaller index = larger key)
    return (((unsigned long long)__float_as_uint(v)) << 32) | (unsigned long long)(~idx);
}

__device__ __forceinline__ void upd2(unsigned long long& a1, unsigned long long& a2,
                                     unsigned long long k) {
    if (k > a1) { a2 = a1; a1 = k; }
    else if (k > a2) { a2 = k; }
}

// merge top-2 list (b1>=b2) into (a1>=a2)
__device__ __forceinline__ void merge2(unsigned long long& a1, unsigned long long& a2,
                                       unsigned long long b1, unsigned long long b2) {
    unsigned long long hi = a1 > b1 ? a1 : b1;
    unsigned long long lo = a1 > b1 ? b1 : a1;
    unsigned long long m2 = a2 > b2 ? a2 : b2;
    a1 = hi;
    a2 = lo > m2 ? lo : m2;
}

// Pass 1: the proven LTS-cap top-2 scan (full unroll, 32 regs).
// Each block triggers programmatic launch completion right after its scratch
// store, releasing the PDL-launched pass2 as early as possible.
__global__ void __launch_bounds__(NTHREADS) pass1_top2(const float* __restrict__ probs) {
    const int tid   = threadIdx.x;
    const int blk   = blockIdx.x;
    const int batch = blk >> 8;        // / BPB
    const int chunk = blk & (BPB - 1);
    const long long row0 = (long long)batch * NA + (long long)chunk * ROWS_PER_BLOCK;
    const float4* __restrict__ p4 = reinterpret_cast<const float4*>(probs);

    unsigned long long k0a = 0, k0b = 0;  // class column 0 (cls=1)
    unsigned long long k1a = 0, k1b = 0;  // class column 1 (cls=2)

#pragma unroll
    for (int it = 0; it < QUADS_PER_THREAD; ++it) {
        const long long row = row0 + (long long)(it * NTHREADS + tid) * 4;
        const long long f4  = (row >> 2) * 3;  // row*3/4, row % 4 == 0
        const float4 A = p4[f4];
        const float4 B = p4[f4 + 1];
        const float4 C = p4[f4 + 2];
        // A = {r0c0,r0c1,r0c2,r1c0}, B = {r1c1,r1c2,r2c0,r2c1}, C = {r2c2,r3c0,r3c1,r3c2}
        const unsigned int i0 = (unsigned int)(row * 2);  // fg flat index of (row, col0)
        upd2(k0a, k0b, make_key(A.y, i0 + 0));
        upd2(k1a, k1b, make_key(A.z, i0 + 1));
        upd2(k0a, k0b, make_key(B.x, i0 + 2));
        upd2(k1a, k1b, make_key(B.y, i0 + 3));
        upd2(k0a, k0b, make_key(B.w, i0 + 4));
        upd2(k1a, k1b, make_key(C.x, i0 + 5));
        upd2(k0a, k0b, make_key(C.z, i0 + 6));
        upd2(k1a, k1b, make_key(C.w, i0 + 7));
    }

    __shared__ unsigned long long s[NTHREADS][4];
    s[tid][0] = k0a;
    s[tid][1] = k0b;
    s[tid][2] = k1a;
    s[tid][3] = k1b;
    __syncthreads();

    for (int off = NTHREADS / 2; off > 0; off >>= 1) {
        if (tid < off) {
            unsigned long long a1 = s[tid][0], a2 = s[tid][1];
            merge2(a1, a2, s[tid + off][0], s[tid + off][1]);
            s[tid][0] = a1; s[tid][1] = a2;
            unsigned long long c1 = s[tid][2], c2 = s[tid][3];
            merge2(c1, c2, s[tid + off][2], s[tid + off][3]);
            s[tid][2] = c1; s[tid][3] = c2;
        }
        __syncthreads();
    }

    if (tid == 0) {
#pragma unroll
        for (int j = 0; j < 4; ++j) g_scratch[blk * 4 + j] = s[0][j];
        __threadfence();
    }
    __syncthreads();
    // PDL: this block is done producing; when all blocks have triggered (or
    // exited), the dependent pass2 may proceed past gridDependencySynchronize.
    cudaTriggerProgrammaticLaunchCompletion();
}

// Pass 2 (PDL secondary): launches concurrently with pass1 and pays its entire
// ramp (scheduling, cold I$/L1) under the 8us scan; blocks here only until the
// primary completes, then does ~1us of real work.
__global__ void __launch_bounds__(256) pass2_decode(const float* __restrict__ anchors,
                                                    const float* __restrict__ deltas,
                                                    float* __restrict__ out) {
    cudaGridDependencySynchronize();   // wait for pass1 (writes visible after)

    __shared__ unsigned long long gtop[16];
    const int tid  = threadIdx.x;
    const int warp = tid >> 5;
    const int lane = tid & 31;

    // 8 warps, one per (batch, class) group
    {
        const int batch = warp >> 1;
        const int col   = warp & 1;
        unsigned long long a1 = 0, a2 = 0;
#pragma unroll
        for (int b = 0; b < BPB / 32; ++b) {
            const int blk = batch * BPB + b * 32 + lane;
            merge2(a1, a2, g_scratch[blk * 4 + col * 2], g_scratch[blk * 4 + col * 2 + 1]);
        }
#pragma unroll
        for (int off = 16; off > 0; off >>= 1) {
            unsigned long long b1 = __shfl_down_sync(0xffffffffu, a1, off);
            unsigned long long b2 = __shfl_down_sync(0xffffffffu, a2, off);
            merge2(a1, a2, b1, b2);
        }
        if (lane == 0) { gtop[warp * 2] = a1; gtop[warp * 2 + 1] = a2; }
    }
    __syncthreads();

    if (tid < 16) {
        // rank sort: all 16 keys distinct (unique index in low bits)
        const unsigned long long key = gtop[tid];
        int rank = 0;
#pragma unroll
        for (int j = 0; j < 16; ++j) rank += (gtop[j] > key) ? 1 : 0;

        const unsigned int flat = ~((unsigned int)key);        // fg flat index
        const int prop = (int)(flat >> 1);
        const int cls  = (int)(flat & 1u) + 1;
        const float score = __uint_as_float((unsigned int)(key >> 32));
        const int b_ix = prop >> 20;           // batch_ixs = repeat(arange(NB), NA)
        const int aidx = prop & (NA - 1);

        const float scale[6] = {256.f, 256.f, 256.f, 256.f, 128.f, 128.f};
        const float stdv[6]  = {0.1f, 0.1f, 0.1f, 0.2f, 0.2f, 0.2f};

        // vectorized gathers: rows are 6 floats = 24B, 8B-aligned -> 3x float2
        const float2* __restrict__ a2p = reinterpret_cast<const float2*>(anchors) +
                                         (long long)aidx * 3;
        const float2* __restrict__ d2p = reinterpret_cast<const float2*>(deltas) +
                                         (long long)prop * 3;
        const float2 av0 = a2p[0], av1 = a2p[1], av2 = a2p[2];
        const float2 dv0 = d2p[0], dv1 = d2p[1], dv2 = d2p[2];

        float anc[6] = {av0.x, av0.y, av1.x, av1.y, av2.x, av2.y};
        float dl [6] = {dv0.x, dv0.y, dv1.x, dv1.y, dv2.x, dv2.y};
#pragma unroll
        for (int j = 0; j < 6; ++j) anc[j] = floorf(anc[j] / scale[j]);
#pragma unroll
        for (int j = 0; j < 6; ++j) dl[j] *= stdv[j];

        float h = anc[2] - anc[0];
        float w = anc[3] - anc[1];
        float d = anc[5] - anc[4];
        float cy = anc[0] + 0.5f * h + dl[0] * h;
        float cx = anc[1] + 0.5f * w + dl[1] * w;
        float cz = anc[4] + 0.5f * d + dl[2] * d;
        h *= expf(dl[3]);
        w *= expf(dl[4]);
        d *= expf(dl[5]);

        float box[6];
        box[0] = cy - 0.5f * h;
        box[1] = cx - 0.5f * w;
        box[2] = box[0] + h;
        box[3] = box[1] + w;
        box[4] = cz - 0.5f * d;
        box[5] = box[4] + d;

        float* o = out + rank * 9;   // each thread writes its sorted slot
#pragma unroll
        for (int j = 0; j < 6; ++j)
            o[j] = rintf(fminf(fmaxf(box[j] * scale[j], 0.0f), scale[j]));
        o[6] = (float)b_ix;
        o[7] = (float)cls;
        o[8] = score;
    }
}

extern "C" void kernel_launch(void* const* d_in, const int* in_sizes, int n_in,
                              void* d_out, int out_size) {
    // identify inputs by element count (robust to ordering)
    const float* anchors = nullptr;   // NA*6       = 6,291,456
    const float* probs   = nullptr;   // NB*NA*3    = 12,582,912
    const float* deltas  = nullptr;   // NB*NA*6    = 25,165,824
    for (int i = 0; i < n_in; ++i) {
        switch (in_sizes[i]) {
            case 6291456:  anchors = (const float*)d_in[i]; break;
            case 12582912: probs   = (const float*)d_in[i]; break;
            case 25165824: deltas  = (const float*)d_in[i]; break;
            default: break;
        }
    }

    pass1_top2<<<NBLOCKS, NTHREADS>>>(probs);

    // PDL launch: pass2 may begin (and pay its ramp) while pass1 runs;
    // it blocks in cudaGridDependencySynchronize() until pass1 completes.
    cudaLaunchConfig_t cfg = {};
    cfg.gridDim  = dim3(1, 1, 1);
    cfg.blockDim = dim3(256, 1, 1);
    cfg.dynamicSmemBytes = 0;
    cfg.stream = 0;
    cudaLaunchAttribute attrs[1];
    attrs[0].id = cudaLaunchAttributeProgrammaticStreamSerialization;
    attrs[0].val.programmaticStreamSerializationAllowed = 1;
    cfg.attrs = attrs;
    cfg.numAttrs = 1;
    cudaError_t e = cudaLaunchKernelEx(&cfg, pass2_decode,
                                       anchors, deltas, (float*)d_out);
    if (e != cudaSuccess) {
        // fallback: plain serialized launch (still correct)
        pass2_decode<<<1, 256>>>(anchors, deltas, (float*)d_out);
    }
}